// round 7
// baseline (speedup 1.0000x reference)
#include <cuda_runtime.h>
#include <math_constants.h>

#define N_NODES 20000
#define N_EDGES 640000
#define FIN     128
#define FQK     128
#define FV      128
#define FTOT    384
#define NHEAD   8
#define FH      16

// ---------------- scratch (device globals; no runtime allocation) ----------
__device__ float g_qkv[N_NODES * FTOT];   // [n][0:128)=q*0.25, [128:256)=k, [256:384)=v
__device__ float g_aw [N_EDGES * NHEAD];  // per-edge per-head logits
__device__ float g_maxw[NHEAD];           // global per-head max
__device__ int   g_src [N_EDGES];         // normalized int32 indices
__device__ int   g_dst [N_EDGES];
__device__ int   g_is64;                  // 1 if ei is int64, 0 if int32

// ---------------- helpers --------------------------------------------------
__device__ __forceinline__ void atomicMaxF(float* addr, float val) {
    int* ai = (int*)addr;
    int old = *ai;
    while (__int_as_float(old) < val) {
        int assumed = old;
        old = atomicCAS(ai, assumed, __float_as_int(val));
        if (old == assumed) break;
    }
}

__device__ __forceinline__ int lower_bound_i(const int* a, int n, int v) {
    int lo = 0, hi = n;
    while (lo < hi) {
        int mid = (lo + hi) >> 1;
        if (a[mid] < v) lo = mid + 1; else hi = mid;
    }
    return lo;
}

// ---------------- kernel A: detect ei dtype + init maxw --------------------
// Interpret ei as int64 and sample indices [E/4, E/4+128) — all inside the
// first (src) region, which exists under BOTH interpretations (int64 src
// occupies bytes [0, 8E); an int32 buffer is 8E bytes total, so reads are
// in-bounds either way). If ei is truly int64: every sampled hi-word is 0 and
// lo-word < N. If ei is int32: the "hi-word" is src[2i+1], a sorted value
// ~N/4 > 0 at these positions -> check fails -> int32.
__global__ void detect_kernel(const unsigned int* ei_w, int E, int nnodes) {
    if (threadIdx.x < NHEAD) g_maxw[threadIdx.x] = -CUDART_INF_F;
    __shared__ int ok;
    if (threadIdx.x == 0) ok = 1;
    __syncthreads();
    int base = E / 4;
    if (threadIdx.x < 128) {
        int i = base + threadIdx.x;
        unsigned int lo = ei_w[2 * i];
        unsigned int hi = ei_w[2 * i + 1];
        if (hi != 0u || lo >= (unsigned int)nnodes) atomicAnd(&ok, 0);
    }
    __syncthreads();
    if (threadIdx.x == 0) g_is64 = ok;
}

// ---------------- kernel B: normalize indices to int32 ---------------------
__global__ void convert_kernel(const void* ei, int E) {
    int i = blockIdx.x * blockDim.x + threadIdx.x;
    if (i >= E) return;
    if (g_is64) {
        const long long* p = (const long long*)ei;
        g_src[i] = (int)p[i];
        g_dst[i] = (int)p[E + i];
    } else {
        const int* p = (const int*)ei;
        g_src[i] = p[i];
        g_dst[i] = p[E + i];
    }
}

// ---------------- kernel 1: proj = x @ W^T (scale q cols by 0.25) ----------
// C[n][c] = sum_k x[n][k] * W[c][k].  Tile 64x64, K chunks of 32.
#define TM 64
#define TN 64
#define TK 32
__global__ __launch_bounds__(256) void gemm_kernel(
    const float* __restrict__ x, const float* __restrict__ W, int nrows)
{
    __shared__ float As[TM][TK + 1];
    __shared__ float Bs[TN][TK + 1];
    const int tid = threadIdx.x;
    const int tx = tid & 15, ty = tid >> 4;
    const int rowBase = blockIdx.x * TM;
    const int colBase = blockIdx.y * TN;

    float acc[4][4] = {};

    for (int k0 = 0; k0 < FIN; k0 += TK) {
        #pragma unroll
        for (int i = 0; i < 8; i++) {
            int idx = tid + i * 256;
            int r = idx >> 5, c = idx & 31;
            int gr = rowBase + r;
            As[r][c] = (gr < nrows) ? x[gr * FIN + k0 + c] : 0.f;
            Bs[r][c] = W[(colBase + r) * FIN + k0 + c];   // 384 % 64 == 0, no guard
        }
        __syncthreads();
        #pragma unroll
        for (int kk = 0; kk < TK; kk++) {
            float a[4], b[4];
            #pragma unroll
            for (int i = 0; i < 4; i++) a[i] = As[ty * 4 + i][kk];
            #pragma unroll
            for (int j = 0; j < 4; j++) b[j] = Bs[tx * 4 + j][kk];
            #pragma unroll
            for (int i = 0; i < 4; i++)
                #pragma unroll
                for (int j = 0; j < 4; j++)
                    acc[i][j] += a[i] * b[j];
        }
        __syncthreads();
    }

    #pragma unroll
    for (int i = 0; i < 4; i++) {
        int gr = rowBase + ty * 4 + i;
        if (gr >= nrows) continue;
        #pragma unroll
        for (int j = 0; j < 4; j++) {
            int gc = colBase + tx * 4 + j;
            float v = acc[i][j];
            if (gc < FQK) v *= 0.25f;   // q scaling = FH^-0.5 = 16^-0.5
            g_qkv[gr * FTOT + gc] = v;
        }
    }
}

// ---------------- kernel 2: per-edge logits + global per-head max ----------
// One warp per edge (grid-stride). Lane l: head h = l>>2, floats [4l, 4l+4).
__global__ __launch_bounds__(256) void edge_kernel(int E)
{
    const int lane   = threadIdx.x & 31;
    const int warp   = (blockIdx.x * blockDim.x + threadIdx.x) >> 5;
    const int nwarps = (gridDim.x * blockDim.x) >> 5;
    const int h = lane >> 2;

    float runmax = -CUDART_INF_F;

    for (int e = warp; e < E; e += nwarps) {
        int s = g_src[e];
        int d = g_dst[e];
        // coalesced 512B reads: q row of s, k row of d
        const float4 qv = *(const float4*)(g_qkv + (size_t)s * FTOT + lane * 4);
        const float4 kv = *(const float4*)(g_qkv + (size_t)d * FTOT + FQK + lane * 4);
        float dot = qv.x * kv.x + qv.y * kv.y + qv.z * kv.z + qv.w * kv.w;
        dot += __shfl_xor_sync(0xFFFFFFFFu, dot, 1);
        dot += __shfl_xor_sync(0xFFFFFFFFu, dot, 2);
        if ((lane & 3) == 0) g_aw[(size_t)e * NHEAD + h] = dot;
        runmax = fmaxf(runmax, dot);
    }

    // hierarchical per-head max: registers -> shared -> global
    __shared__ float smax[NHEAD];
    if (threadIdx.x < NHEAD) smax[threadIdx.x] = -CUDART_INF_F;
    __syncthreads();
    if ((lane & 3) == 0 && runmax > -CUDART_INF_F) atomicMaxF(&smax[h], runmax);
    __syncthreads();
    if (threadIdx.x < NHEAD && smax[threadIdx.x] > -CUDART_INF_F)
        atomicMaxF(&g_maxw[threadIdx.x], smax[threadIdx.x]);
}

// ---------------- kernel 3: per-node softmax-weighted aggregation ----------
// One warp per node. src sorted => node n owns contiguous edge range.
// out[n] = sum_e (exp(aw-mx)+1e-8) * v[dst[e]] / sum_e (exp(aw-mx)+1e-8)
__global__ __launch_bounds__(256) void node_kernel(
    float* __restrict__ out, int nnodes, int E)
{
    const int lane = threadIdx.x & 31;
    const int n    = (blockIdx.x * blockDim.x + threadIdx.x) >> 5;
    if (n >= nnodes) return;

    int lo = 0, hi = 0;
    if (lane == 0) {
        lo = lower_bound_i(g_src, E, n);
        hi = lower_bound_i(g_src, E, n + 1);
    }
    lo = __shfl_sync(0xFFFFFFFFu, lo, 0);
    hi = __shfl_sync(0xFFFFFFFFu, hi, 0);

    const int h = lane >> 2;
    const float mx = g_maxw[h];

    float4 acc = make_float4(0.f, 0.f, 0.f, 0.f);
    float sum = 0.f;

    for (int e = lo; e < hi; e++) {
        float a = __ldg(&g_aw[(size_t)e * NHEAD + h]);
        float w = __expf(a - mx) + 1e-8f;
        sum += w;
        int d = g_dst[e];
        const float4 vv = *(const float4*)(g_qkv + (size_t)d * FTOT + 2 * FQK + lane * 4);
        acc.x += w * vv.x;
        acc.y += w * vv.y;
        acc.z += w * vv.z;
        acc.w += w * vv.w;
    }

    float inv = (hi > lo) ? (1.f / sum) : 0.f;
    float4 res = make_float4(acc.x * inv, acc.y * inv, acc.z * inv, acc.w * inv);
    ((float4*)out)[(size_t)n * 32 + lane] = res;   // coalesced 512B store per warp
}

// ---------------- launch ---------------------------------------------------
extern "C" void kernel_launch(void* const* d_in, const int* in_sizes, int n_in,
                              void* d_out, int out_size)
{
    const float* x  = (const float*)d_in[0];          // [N, 128]
    const float* W  = (const float*)d_in[1];          // [384, 128]
    // d_in[2] = batch (unused by reference math)
    const void*  ei = d_in[3];                        // [2, E], int32 or int64
    float* out = (float*)d_out;

    const int nrows = in_sizes[0] / FIN;
    const int E     = in_sizes[3] / 2;

    detect_kernel<<<1, 128>>>((const unsigned int*)ei, E, nrows);
    convert_kernel<<<(E + 255) / 256, 256>>>(ei, E);

    dim3 ggrid((nrows + TM - 1) / TM, FTOT / TN);
    gemm_kernel<<<ggrid, 256>>>(x, W, nrows);

    edge_kernel<<<2048, 256>>>(E);

    int nblocks = (nrows * 32 + 255) / 256;
    node_kernel<<<nblocks, 256>>>(out, nrows, E);
}

// round 9
// speedup vs baseline: 1.2347x; 1.2347x over previous
#include <cuda_runtime.h>
#include <math_constants.h>

#define N_NODES 20000
#define N_EDGES 640000
#define FIN     128
#define FQK     128
#define FV      128
#define FTOT    384
#define NHEAD   8
#define FH      16

// ---------------- scratch (device globals; no runtime allocation) ----------
__device__ float g_qkv[N_NODES * FTOT];   // [n][0:128)=q*0.25, [128:256)=k, [256:384)=v
__device__ float g_aw [N_EDGES * NHEAD];  // per-edge per-head logits
__device__ float g_maxw[NHEAD];           // global per-head max
__device__ int   g_src [N_EDGES];         // normalized int32 indices
__device__ int   g_dst [N_EDGES];
__device__ int   g_is64;                  // 1 if ei is int64, 0 if int32

// ---------------- helpers --------------------------------------------------
__device__ __forceinline__ void atomicMaxF(float* addr, float val) {
    int* ai = (int*)addr;
    int old = *ai;
    while (__int_as_float(old) < val) {
        int assumed = old;
        old = atomicCAS(ai, assumed, __float_as_int(val));
        if (old == assumed) break;
    }
}

__device__ __forceinline__ int lower_bound_i(const int* a, int n, int v) {
    int lo = 0, hi = n;
    while (lo < hi) {
        int mid = (lo + hi) >> 1;
        if (a[mid] < v) lo = mid + 1; else hi = mid;
    }
    return lo;
}

__device__ __forceinline__ unsigned long long packdup(float a) {
    unsigned long long r;
    asm("mov.b64 %0, {%1, %1};" : "=l"(r) : "f"(a));
    return r;
}
__device__ __forceinline__ void ffma2(unsigned long long& acc,
                                      unsigned long long a, unsigned long long b) {
    asm("fma.rn.f32x2 %0, %1, %2, %0;" : "+l"(acc) : "l"(a), "l"(b));
}
__device__ __forceinline__ void unpack2(unsigned long long p, float& lo, float& hi) {
    asm("mov.b64 {%0, %1}, %2;" : "=f"(lo), "=f"(hi) : "l"(p));
}

// ---------------- kernel A: detect ei dtype + init maxw --------------------
// Sample int64-interpreted words from the middle of the src region (in-bounds
// under both interpretations). int64 => hi-words 0, lo-word < N. int32 =>
// the "hi-word" is a sorted src value ~N/4 > 0 -> check fails.
__global__ void detect_kernel(const unsigned int* ei_w, int E, int nnodes) {
    if (threadIdx.x < NHEAD) g_maxw[threadIdx.x] = -CUDART_INF_F;
    __shared__ int ok;
    if (threadIdx.x == 0) ok = 1;
    __syncthreads();
    int base = E / 4;
    if (threadIdx.x < 128) {
        int i = base + threadIdx.x;
        unsigned int lo = ei_w[2 * i];
        unsigned int hi = ei_w[2 * i + 1];
        if (hi != 0u || lo >= (unsigned int)nnodes) atomicAnd(&ok, 0);
    }
    __syncthreads();
    if (threadIdx.x == 0) g_is64 = ok;
}

// ---------------- kernel B: normalize indices to int32 ---------------------
__global__ void convert_kernel(const void* ei, int E) {
    int i = blockIdx.x * blockDim.x + threadIdx.x;
    if (i >= E) return;
    if (g_is64) {
        const long long* p = (const long long*)ei;
        g_src[i] = (int)p[i];
        g_dst[i] = (int)p[E + i];
    } else {
        const int* p = (const int*)ei;
        g_src[i] = p[i];
        g_dst[i] = p[E + i];
    }
}

// ---------------- kernel 1: proj = x @ W^T  (packed f32x2 FMAs) ------------
// C[n][c] = sum_k x[n][k]*W[c][k]. Tile 64x128, K chunks of 32, 4x8 microtile.
// Thread (tx,ty): rows ty*4+i, cols tx*2 + j2*32 + {0,1}  (j2 = 0..3).
#define TM 64
#define TN 128
#define TK 32
#define BS_STRIDE (TN + 2)   // even => 8B-aligned LDS.64; 2-way STS conflict ok
#define AS_STRIDE (TM + 1)

__global__ __launch_bounds__(256) void gemm_kernel(
    const float* __restrict__ x, const float* __restrict__ W, int nrows)
{
    __shared__ float As[TK][AS_STRIDE];   // As[kk][row]
    __shared__ float Bs[TK][BS_STRIDE];   // Bs[kk][col]
    const int tid = threadIdx.x;
    const int tx = tid & 15, ty = tid >> 4;
    const int rowBase = blockIdx.x * TM;
    const int colBase = blockIdx.y * TN;

    unsigned long long acc2[4][4];
    #pragma unroll
    for (int i = 0; i < 4; i++)
        #pragma unroll
        for (int j = 0; j < 4; j++) acc2[i][j] = 0ull;

    const int lr = tid >> 5;        // 0..7
    const int lc = tid & 31;        // 0..31

    for (int k0 = 0; k0 < FIN; k0 += TK) {
        // load A tile: 64 rows x 32 k -> As[k][row]
        #pragma unroll
        for (int i = 0; i < 8; i++) {
            int r = lr + i * 8;
            int gr = rowBase + r;
            As[lc][r] = (gr < nrows) ? x[(size_t)gr * FIN + k0 + lc] : 0.f;
        }
        // load B tile: 128 rows(cols of C) x 32 k -> Bs[k][col]
        #pragma unroll
        for (int i = 0; i < 16; i++) {
            int r = lr + i * 8;
            Bs[lc][r] = W[(size_t)(colBase + r) * FIN + k0 + lc];
        }
        __syncthreads();

        #pragma unroll
        for (int kk = 0; kk < TK; kk++) {
            unsigned long long ap[4];
            #pragma unroll
            for (int i = 0; i < 4; i++) ap[i] = packdup(As[kk][ty * 4 + i]);
            unsigned long long bp[4];
            #pragma unroll
            for (int j = 0; j < 4; j++)
                bp[j] = *(const unsigned long long*)&Bs[kk][tx * 2 + j * 32];
            #pragma unroll
            for (int i = 0; i < 4; i++)
                #pragma unroll
                for (int j = 0; j < 4; j++)
                    ffma2(acc2[i][j], ap[i], bp[j]);
        }
        __syncthreads();
    }

    const float scale = (colBase == 0) ? 0.25f : 1.0f;  // q block gets FH^-0.5
    #pragma unroll
    for (int i = 0; i < 4; i++) {
        int gr = rowBase + ty * 4 + i;
        if (gr >= nrows) continue;
        #pragma unroll
        for (int j = 0; j < 4; j++) {
            float v0, v1;
            unpack2(acc2[i][j], v0, v1);
            int gc = colBase + tx * 2 + j * 32;
            g_qkv[(size_t)gr * FTOT + gc]     = v0 * scale;
            g_qkv[(size_t)gr * FTOT + gc + 1] = v1 * scale;
        }
    }
}

// ---------------- kernel 2: per-edge logits + global per-head max ----------
// One warp per contiguous 32-edge block; 4 edges per iteration (MLP=8 loads).
// Lane l: head h = l>>2, floats [4l, 4l+4).
__device__ __forceinline__ float edge_dot(int s, int d, int lane) {
    const float4 qv = *(const float4*)(g_qkv + (size_t)s * FTOT + lane * 4);
    const float4 kv = *(const float4*)(g_qkv + (size_t)d * FTOT + FQK + lane * 4);
    return qv.x * kv.x + qv.y * kv.y + qv.z * kv.z + qv.w * kv.w;
}

__global__ __launch_bounds__(256) void edge_kernel(int E)
{
    const int lane = threadIdx.x & 31;
    const int warp = (blockIdx.x * blockDim.x + threadIdx.x) >> 5;
    const int h = lane >> 2;
    const int e0  = warp * 32;
    const int end = min(e0 + 32, E);

    float runmax = -CUDART_INF_F;

    int e = e0;
    for (; e + 4 <= end; e += 4) {
        int s0 = g_src[e],     d0 = g_dst[e];
        int s1 = g_src[e + 1], d1 = g_dst[e + 1];
        int s2 = g_src[e + 2], d2 = g_dst[e + 2];
        int s3 = g_src[e + 3], d3 = g_dst[e + 3];
        float t0 = edge_dot(s0, d0, lane);
        float t1 = edge_dot(s1, d1, lane);
        float t2 = edge_dot(s2, d2, lane);
        float t3 = edge_dot(s3, d3, lane);
        t0 += __shfl_xor_sync(0xFFFFFFFFu, t0, 1);
        t1 += __shfl_xor_sync(0xFFFFFFFFu, t1, 1);
        t2 += __shfl_xor_sync(0xFFFFFFFFu, t2, 1);
        t3 += __shfl_xor_sync(0xFFFFFFFFu, t3, 1);
        t0 += __shfl_xor_sync(0xFFFFFFFFu, t0, 2);
        t1 += __shfl_xor_sync(0xFFFFFFFFu, t1, 2);
        t2 += __shfl_xor_sync(0xFFFFFFFFu, t2, 2);
        t3 += __shfl_xor_sync(0xFFFFFFFFu, t3, 2);
        if ((lane & 3) == 0) {
            g_aw[(size_t)(e    ) * NHEAD + h] = t0;
            g_aw[(size_t)(e + 1) * NHEAD + h] = t1;
            g_aw[(size_t)(e + 2) * NHEAD + h] = t2;
            g_aw[(size_t)(e + 3) * NHEAD + h] = t3;
        }
        runmax = fmaxf(runmax, fmaxf(fmaxf(t0, t1), fmaxf(t2, t3)));
    }
    for (; e < end; e++) {
        float t = edge_dot(g_src[e], g_dst[e], lane);
        t += __shfl_xor_sync(0xFFFFFFFFu, t, 1);
        t += __shfl_xor_sync(0xFFFFFFFFu, t, 2);
        if ((lane & 3) == 0) g_aw[(size_t)e * NHEAD + h] = t;
        runmax = fmaxf(runmax, t);
    }

    // hierarchical per-head max: registers -> shared -> global
    __shared__ float smax[NHEAD];
    if (threadIdx.x < NHEAD) smax[threadIdx.x] = -CUDART_INF_F;
    __syncthreads();
    if ((lane & 3) == 0 && runmax > -CUDART_INF_F) atomicMaxF(&smax[h], runmax);
    __syncthreads();
    if (threadIdx.x < NHEAD && smax[threadIdx.x] > -CUDART_INF_F)
        atomicMaxF(&g_maxw[threadIdx.x], smax[threadIdx.x]);
}

// ---------------- kernel 3: per-node softmax-weighted aggregation ----------
// One warp per node; src sorted => node n owns a contiguous edge range.
__global__ __launch_bounds__(256) void node_kernel(
    float* __restrict__ out, int nnodes, int E)
{
    const int lane = threadIdx.x & 31;
    const int n    = (blockIdx.x * blockDim.x + threadIdx.x) >> 5;
    if (n >= nnodes) return;

    int lo = 0, hi = 0;
    if (lane == 0) {
        lo = lower_bound_i(g_src, E, n);
        hi = lower_bound_i(g_src, E, n + 1);
    }
    lo = __shfl_sync(0xFFFFFFFFu, lo, 0);
    hi = __shfl_sync(0xFFFFFFFFu, hi, 0);

    const int h = lane >> 2;
    const float mx = g_maxw[h];

    float4 acc = make_float4(0.f, 0.f, 0.f, 0.f);
    float sum = 0.f;

    int e = lo;
    for (; e + 4 <= hi; e += 4) {
        int d0 = g_dst[e], d1 = g_dst[e + 1], d2 = g_dst[e + 2], d3 = g_dst[e + 3];
        float a0 = g_aw[(size_t)(e    ) * NHEAD + h];
        float a1 = g_aw[(size_t)(e + 1) * NHEAD + h];
        float a2 = g_aw[(size_t)(e + 2) * NHEAD + h];
        float a3 = g_aw[(size_t)(e + 3) * NHEAD + h];
        const float4 v0 = *(const float4*)(g_qkv + (size_t)d0 * FTOT + 2 * FQK + lane * 4);
        const float4 v1 = *(const float4*)(g_qkv + (size_t)d1 * FTOT + 2 * FQK + lane * 4);
        const float4 v2 = *(const float4*)(g_qkv + (size_t)d2 * FTOT + 2 * FQK + lane * 4);
        const float4 v3 = *(const float4*)(g_qkv + (size_t)d3 * FTOT + 2 * FQK + lane * 4);
        float w0 = __expf(a0 - mx) + 1e-8f;
        float w1 = __expf(a1 - mx) + 1e-8f;
        float w2 = __expf(a2 - mx) + 1e-8f;
        float w3 = __expf(a3 - mx) + 1e-8f;
        sum += (w0 + w1) + (w2 + w3);
        acc.x += w0 * v0.x + w1 * v1.x + w2 * v2.x + w3 * v3.x;
        acc.y += w0 * v0.y + w1 * v1.y + w2 * v2.y + w3 * v3.y;
        acc.z += w0 * v0.z + w1 * v1.z + w2 * v2.z + w3 * v3.z;
        acc.w += w0 * v0.w + w1 * v1.w + w2 * v2.w + w3 * v3.w;
    }
    for (; e < hi; e++) {
        float a = g_aw[(size_t)e * NHEAD + h];
        float w = __expf(a - mx) + 1e-8f;
        sum += w;
        int d = g_dst[e];
        const float4 vv = *(const float4*)(g_qkv + (size_t)d * FTOT + 2 * FQK + lane * 4);
        acc.x += w * vv.x;
        acc.y += w * vv.y;
        acc.z += w * vv.z;
        acc.w += w * vv.w;
    }

    float inv = (hi > lo) ? (1.f / sum) : 0.f;
    float4 res = make_float4(acc.x * inv, acc.y * inv, acc.z * inv, acc.w * inv);
    ((float4*)out)[(size_t)n * 32 + lane] = res;   // coalesced 512B store per warp
}

// ---------------- launch ---------------------------------------------------
extern "C" void kernel_launch(void* const* d_in, const int* in_sizes, int n_in,
                              void* d_out, int out_size)
{
    const float* x  = (const float*)d_in[0];          // [N, 128]
    const float* W  = (const float*)d_in[1];          // [384, 128]
    // d_in[2] = batch (unused by reference math)
    const void*  ei = d_in[3];                        // [2, E], int32 or int64
    float* out = (float*)d_out;

    const int nrows = in_sizes[0] / FIN;
    const int E     = in_sizes[3] / 2;

    detect_kernel<<<1, 128>>>((const unsigned int*)ei, E, nrows);
    convert_kernel<<<(E + 255) / 256, 256>>>(ei, E);

    dim3 ggrid((nrows + TM - 1) / TM, FTOT / TN);
    gemm_kernel<<<ggrid, 256>>>(x, W, nrows);

    int eblocks = (E + 255) / 256;                    // 8 warps/block, 32 edges/warp
    edge_kernel<<<eblocks, 256>>>(E);

    int nblocks = (nrows * 32 + 255) / 256;
    node_kernel<<<nblocks, 256>>>(out, nrows, E);
}